// round 8
// baseline (speedup 1.0000x reference)
#include <cuda_runtime.h>
#include <cuda_bf16.h>

// Problem constants
#define BSZ 64
#define KREG 19
#define KALL 20          // 19 regions + 1 global (all-ones weight row)
#define CCH 384
#define PPIX 256         // 16x16
#define DOUT 256
#define NROWS (BSZ * KALL)   // 1280

// Scratch (device globals; no allocation allowed)
__device__ float g_wsmall[BSZ * KALL * PPIX];     // [b][k][p]
__device__ float g_allfeats[NROWS * CCH];         // [row][c]
__device__ float g_Wt[CCH * DOUT];                // [c][d]

typedef unsigned long long ull;

// ---- packed f32x2 helpers (Blackwell) --------------------------------------
__device__ __forceinline__ ull pack2(float lo, float hi) {
    ull r;
    asm("mov.b64 %0, {%1, %2};" : "=l"(r) : "f"(lo), "f"(hi));
    return r;
}
__device__ __forceinline__ void unpack2(ull v, float& lo, float& hi) {
    asm("mov.b64 {%0, %1}, %2;" : "=f"(lo), "=f"(hi) : "l"(v));
}
__device__ __forceinline__ ull ffma2(ull a, ull b, ull c) {
    ull d;
    asm("fma.rn.f32x2 %0, %1, %2, %3;" : "=l"(d) : "l"(a), "l"(b), "l"(c));
    return d;
}

// ---------------------------------------------------------------------------
// kA: merged prep kernel.
//  blocks [0,304):    downsample, FOUR (b,k) region tiles per block (MLP=16)
//  blocks [304,400):  W transpose -> g_Wt [c][d]
//  blocks [400,408):  all-ones rows (k=19)
// Downsample: out(i,j) = 0.25*(s[16i+7][16j+7]+s[16i+7][16j+8]
//                             +s[16i+8][16j+7]+s[16i+8][16j+8])
// ---------------------------------------------------------------------------
#define KA_T 4
__global__ __launch_bounds__(256)
void kA_prep(const float* __restrict__ seg, const float* __restrict__ W) {
    int bx = blockIdx.x;
    int t = threadIdx.x;

    if (bx < 304) {
        __shared__ float smk[KA_T][32 * 34];
        int r = t >> 3;              // 0..31 smem row
        int lane8 = t & 7;
        int gi = r >> 1;
        int grow = 16 * gi + 7 + (r & 1);

        float4 v[KA_T][4];
#pragma unroll
        for (int s2 = 0; s2 < KA_T; s2++) {
            int rk = bx * KA_T + s2;            // 0..1215
            const float4* row4 = reinterpret_cast<const float4*>(
                seg + ((size_t)rk * 256 + grow) * 256);
#pragma unroll
            for (int u = 0; u < 4; u++) {
                int s = lane8 + 8 * u;
                int f = 4 * (s >> 1) + 1 + (s & 1);
                v[s2][u] = row4[f];
            }
        }
#pragma unroll
        for (int s2 = 0; s2 < KA_T; s2++)
#pragma unroll
            for (int u = 0; u < 4; u++) {
                int s = lane8 + 8 * u;
                smk[s2][r * 34 + s] = (s & 1) ? v[s2][u].x : v[s2][u].w;
            }
        __syncthreads();

        int i = t >> 4, j = t & 15;
#pragma unroll
        for (int s2 = 0; s2 < KA_T; s2++) {
            int rk = bx * KA_T + s2;
            int b = rk / KREG, k = rk - b * KREG;
            const float2* lo2 = reinterpret_cast<const float2*>(
                smk[s2] + (2 * i) * 34 + 2 * j);
            const float2* hi2 = reinterpret_cast<const float2*>(
                smk[s2] + (2 * i + 1) * 34 + 2 * j);
            float2 a = *lo2, c = *hi2;
            g_wsmall[(b * KALL + k) * PPIX + t] = 0.25f * (a.x + a.y + c.x + c.y);
        }
    } else if (bx < 400) {
        __shared__ float ts[32][33];
        int id = bx - 304;            // 0..95
        int c0 = (id % 12) * 32;
        int d0 = (id / 12) * 32;
        int tx = t & 31, ty = t >> 5; // 32 x 8
#pragma unroll
        for (int i = 0; i < 4; i++)
            ts[ty + 8 * i][tx] = W[(d0 + ty + 8 * i) * CCH + c0 + tx];
        __syncthreads();
#pragma unroll
        for (int i = 0; i < 4; i++)
            g_Wt[(c0 + ty + 8 * i) * DOUT + d0 + tx] = ts[tx][ty + 8 * i];
    } else {
        // ones rows: 64 b x 256 p = 4096 float4
        int e4 = (bx - 400) * 512 + t;
#pragma unroll
        for (int it = 0; it < 2; it++, e4 += 256) {
            int b = e4 >> 6;               // 64 float4 per b
            int p4 = e4 & 63;
            float4* dst = reinterpret_cast<float4*>(
                g_wsmall + (b * KALL + KREG) * PPIX + p4 * 4);
            *dst = make_float4(1.f, 1.f, 1.f, 1.f);
        }
    }
}

// ---------------------------------------------------------------------------
// K2 v2: per-batch GEMM  A[b] = (1/256) * w[20 x 256] * F[b]^T[256 x 384]
//  grid (64, 3), 256 threads. Block tile: 20 k x 128 c, full p=256.
//  4 p-groups x 64 c-pair threads; thread: 10 k-pairs x 1 c-pair over its
//  64 p's. w-pairs are native LDS.64 (broadcast), f duplicated via pack.
//  Register-prefetch single-buffer F staging; smem tree-reduce over p-groups.
// ---------------------------------------------------------------------------
__global__ __launch_bounds__(256)
void k2_region_gemm(const float* __restrict__ F) {
    __shared__ float sm[10240];           // 40 KB
    float* ws = sm;                       // [p][k] 256*20 = 5120 floats
    float* fs = sm + 5120;                // [32 p][130] = 4160 floats
    float2* red = reinterpret_cast<float2*>(sm);  // [4][1280] float2 (reuse)

    int b = blockIdx.x;
    int c0 = blockIdx.y * 128;
    int t = threadIdx.x;                // 256
    int pg = t >> 6;                    // p-group 0..3
    int cgp = t & 63;                   // c-pair index: cols (2cgp, 2cgp+1)

    // stage w_small[b] transposed -> ws[p][k]
    const float* wsm = g_wsmall + b * KALL * PPIX;
    for (int idx = t; idx < KALL * PPIX; idx += 256) {
        int k = idx >> 8, p = idx & 255;
        ws[p * KALL + k] = wsm[idx];
    }

    const float* Fb = F + ((size_t)b * CCH + c0) * PPIX;

    // prefetch F chunk 0 (32 p x 128 c = 1024 float4, 4/thread)
    float4 pf[4];
#pragma unroll
    for (int r = 0; r < 4; r++) {
        int linear = r * 256 + t;
        int c = linear >> 3;
        int p4 = linear & 7;
        pf[r] = *reinterpret_cast<const float4*>(Fb + c * PPIX + p4 * 4);
    }

    ull acc[10][2];
#pragma unroll
    for (int i = 0; i < 10; i++) { acc[i][0] = 0ull; acc[i][1] = 0ull; }

    for (int ch = 0; ch < 8; ch++) {
        if (ch) __syncthreads();        // prior chunk's reads complete
#pragma unroll
        for (int r = 0; r < 4; r++) {
            int linear = r * 256 + t;
            int c = linear >> 3;
            int p4 = linear & 7;
            fs[(p4 * 4 + 0) * 130 + c] = pf[r].x;
            fs[(p4 * 4 + 1) * 130 + c] = pf[r].y;
            fs[(p4 * 4 + 2) * 130 + c] = pf[r].z;
            fs[(p4 * 4 + 3) * 130 + c] = pf[r].w;
        }
        __syncthreads();
        if (ch < 7) {
#pragma unroll
            for (int r = 0; r < 4; r++) {
                int linear = r * 256 + t;
                int c = linear >> 3;
                int p4 = linear & 7;
                pf[r] = *reinterpret_cast<const float4*>(
                    Fb + c * PPIX + (ch + 1) * 32 + p4 * 4);
            }
        }

        int pc = ch * 32;
#pragma unroll
        for (int pp = 0; pp < 8; pp++) {
            int pl = pg * 8 + pp;              // p within chunk
            const float* wr = ws + (pc + pl) * KALL;
            ull f2 = *reinterpret_cast<const ull*>(fs + pl * 130 + 2 * cgp);
            float f0, f1;
            unpack2(f2, f0, f1);
            ull fd0 = pack2(f0, f0);
            ull fd1 = pack2(f1, f1);
#pragma unroll
            for (int ki = 0; ki < 10; ki++) {
                ull w2 = *reinterpret_cast<const ull*>(wr + 2 * ki);  // broadcast
                acc[ki][0] = ffma2(w2, fd0, acc[ki][0]);
                acc[ki][1] = ffma2(w2, fd1, acc[ki][1]);
            }
        }
    }

    // tree reduce over 4 p-groups via smem (reuses ws/fs region)
    __syncthreads();
#pragma unroll
    for (int ki = 0; ki < 10; ki++) {
#pragma unroll
        for (int cc = 0; cc < 2; cc++) {
            float lo, hi;
            unpack2(acc[ki][cc], lo, hi);
            red[pg * 1280 + ki * 128 + 2 * cgp + cc] = make_float2(lo, hi);
        }
    }
    __syncthreads();

    const float inv = 1.0f / 256.0f;
    float* A = g_allfeats + (size_t)(b * KALL) * CCH + c0;
#pragma unroll
    for (int j = 0; j < 5; j++) {
        int i = t + 256 * j;                  // 0..1279
        float2 s0 = red[i];
        float2 s1 = red[1280 + i];
        float2 s2 = red[2560 + i];
        float2 s3 = red[3840 + i];
        float lo = (s0.x + s1.x) + (s2.x + s3.x);
        float hi = (s0.y + s1.y) + (s2.y + s3.y);
        int kp = i >> 7;                      // k pair (2kp, 2kp+1)
        int col = i & 127;
        A[(2 * kp) * CCH + col]     = lo * inv;
        A[(2 * kp + 1) * CCH + col] = hi * inv;
    }
}

// ---------------------------------------------------------------------------
// K3 v4: single-pass projection  out = relu(A[1280x384] * Wt + bias)
//  grid (40 row-blocks, 4 d-splits of 64), 256 threads, full K=384.
//  Thread: 4 rows (2 packed pairs) x 2 d.  A staged [k][r] (pad 36) ->
//  broadcast LDS.128 gives 2 native row-pairs; W staged DUPLICATED
//  ([k][2d], pad 130) -> one LDS.64 per d. 7 instr / 8 FMA lanes.
//  Double-buffered chunks (32 k) with register prefetch.
// ---------------------------------------------------------------------------
#define K3_RB  32
#define K3_KC  32
#define K3_NCH (CCH / K3_KC)     // 12

__global__ __launch_bounds__(256)
void k3_project(const float* __restrict__ bias, float* __restrict__ out) {
    __shared__ float asf[2][K3_KC * 36];       // [buf][kk][r(pad 36)]  2x4.6KB
    __shared__ float wdup[2][K3_KC * 130];     // [buf][kk][2d dup(pad 130)] 2x16.6KB

    int t = threadIdx.x;
    int rg = t >> 5;            // 0..7 -> rows rg*4 .. rg*4+3
    int dg = t & 31;            // d in {dg, dg+32} of this 64-d tile
    int row0 = blockIdx.x * K3_RB;
    int d0 = blockIdx.y * 64;

    // per-thread staging coords
    int ar = t >> 3;            // A: row index 0..31
    int aq = t & 7;             // A: k-quad 0..7 -> kk = 4*aq..+3
    int wk = t >> 4;            // W: kk 0..15 (+16 on second pass)
    int wc = t & 15;            // W: float4 index within 64-d row

    const float* Ab = g_allfeats + (size_t)row0 * CCH;
    const float* Wb = g_Wt + d0;

    // prefetch chunk 0
    float4 pa, pw0, pw1;
    pa  = *reinterpret_cast<const float4*>(Ab + ar * CCH + aq * 4);
    pw0 = *reinterpret_cast<const float4*>(Wb + (size_t)wk * DOUT + wc * 4);
    pw1 = *reinterpret_cast<const float4*>(Wb + (size_t)(wk + 16) * DOUT + wc * 4);

    ull acc00 = 0, acc01 = 0, acc10 = 0, acc11 = 0;

    for (int ch = 0; ch < K3_NCH; ch++) {
        int buf = ch & 1;
        // commit prefetched data
        {
            float* as = asf[buf];
            as[(4 * aq + 0) * 36 + ar] = pa.x;
            as[(4 * aq + 1) * 36 + ar] = pa.y;
            as[(4 * aq + 2) * 36 + ar] = pa.z;
            as[(4 * aq + 3) * 36 + ar] = pa.w;
            float* wd = wdup[buf];
            float2* w2p;
            w2p = reinterpret_cast<float2*>(wd + wk * 130 + 2 * (4 * wc));
            w2p[0] = make_float2(pw0.x, pw0.x);
            w2p[1] = make_float2(pw0.y, pw0.y);
            w2p[2] = make_float2(pw0.z, pw0.z);
            w2p[3] = make_float2(pw0.w, pw0.w);
            w2p = reinterpret_cast<float2*>(wd + (wk + 16) * 130 + 2 * (4 * wc));
            w2p[0] = make_float2(pw1.x, pw1.x);
            w2p[1] = make_float2(pw1.y, pw1.y);
            w2p[2] = make_float2(pw1.z, pw1.z);
            w2p[3] = make_float2(pw1.w, pw1.w);
        }
        __syncthreads();

        // issue next chunk's loads (latency overlapped with compute)
        if (ch + 1 < K3_NCH) {
            int kb = (ch + 1) * K3_KC;
            pa  = *reinterpret_cast<const float4*>(Ab + ar * CCH + kb + aq * 4);
            pw0 = *reinterpret_cast<const float4*>(Wb + (size_t)(kb + wk) * DOUT + wc * 4);
            pw1 = *reinterpret_cast<const float4*>(Wb + (size_t)(kb + wk + 16) * DOUT + wc * 4);
        }

        const float* as = asf[buf];
        const float* wd = wdup[buf];
#pragma unroll
        for (int kk = 0; kk < K3_KC; kk++) {
            ulonglong2 a2 = *reinterpret_cast<const ulonglong2*>(as + kk * 36 + rg * 4);
            ull w0 = *reinterpret_cast<const ull*>(wd + kk * 130 + 2 * dg);
            ull w1 = *reinterpret_cast<const ull*>(wd + kk * 130 + 2 * (dg + 32));
            acc00 = ffma2(a2.x, w0, acc00);
            acc01 = ffma2(a2.x, w1, acc01);
            acc10 = ffma2(a2.y, w0, acc10);
            acc11 = ffma2(a2.y, w1, acc11);
        }
        __syncthreads();   // reads done before this buffer is overwritten
    }

    // epilogue: bias + relu
    float b0 = bias[d0 + dg];
    float b1 = bias[d0 + dg + 32];
    float v00, v01, v10, v11, v20, v21, v30, v31;
    unpack2(acc00, v00, v10);   // rows rg*4, rg*4+1 @ d=dg
    unpack2(acc01, v01, v11);   // rows rg*4, rg*4+1 @ d=dg+32
    unpack2(acc10, v20, v30);   // rows rg*4+2, rg*4+3 @ d=dg
    unpack2(acc11, v21, v31);   // rows rg*4+2, rg*4+3 @ d=dg+32

    int r = row0 + rg * 4;
    float* o0 = out + (size_t)r * DOUT + d0;
    o0[dg]                 = fmaxf(v00 + b0, 0.0f);
    o0[dg + 32]            = fmaxf(v01 + b1, 0.0f);
    o0[DOUT + dg]          = fmaxf(v10 + b0, 0.0f);
    o0[DOUT + dg + 32]     = fmaxf(v11 + b1, 0.0f);
    o0[2 * DOUT + dg]      = fmaxf(v20 + b0, 0.0f);
    o0[2 * DOUT + dg + 32] = fmaxf(v21 + b1, 0.0f);
    o0[3 * DOUT + dg]      = fmaxf(v30 + b0, 0.0f);
    o0[3 * DOUT + dg + 32] = fmaxf(v31 + b1, 0.0f);
}

// ---------------------------------------------------------------------------
extern "C" void kernel_launch(void* const* d_in, const int* in_sizes, int n_in,
                              void* d_out, int out_size) {
    const float* F    = (const float*)d_in[0];   // [64,384,16,16]
    const float* seg  = (const float*)d_in[1];   // [64,19,256,256]
    const float* W    = (const float*)d_in[2];   // [256,384]
    const float* bias = (const float*)d_in[3];   // [256]
    float* out = (float*)d_out;                  // [64, 5120]

    kA_prep<<<408, 256>>>(seg, W);
    k2_region_gemm<<<dim3(BSZ, 3), 256>>>(F);
    k3_project<<<dim3(40, 4), 256>>>(bias, out);
}